// round 13
// baseline (speedup 1.0000x reference)
#include <cuda_runtime.h>
#include <cuda_bf16.h>
#include <cuda_fp16.h>
#include <cstdint>

#define B_ 2
#define N_ 7
#define C_ 128
#define H_ 120
#define W_ 360
#define HW_ (H_*W_)
#define HID_ 128
#define OCOFF_ 56

// conv1 mma geometry (single fp16 A, single fp16 B)
#define KP_ 960                    // padded K (898 -> 960, 15 chunks of 64)
#define HP_ 122
#define WP_ 372
#define ASZ_ 16640                 // A tile: 130 rows x 128B
#define BSZ_ 16384                 // B tile: 128 rows x 128B
#define NGRP_ 45                   // 15 kc x 3 ky
#define NSTG_ 135                  // 45 groups x 3 kx stages
#define SMEM_CONV_ (2*ASZ_ + 2*BSZ_)   // 66048B

// offconv mma geometry (K = 128 lr + 48 sim + 16 pad = 192; N = 56 -> 64)
#define KO_ 192
#define OBSZ_ 8192                 // B tile: 64 rows x 128B
#define ONSTG_ 27                  // 9 groups (3 kc x 3 ky) x 3 kx
#define SMEM_OFF_ (2*ASZ_ + 2*OBSZ_)   // 49664B

// ---------------- scratch (device globals; no runtime alloc) ----------------
__device__ float g_mean[B_*C_*HW_];
__device__ float g_norm[B_*HW_];
__device__ float g_feat[B_*HID_*HW_];
__device__ float g_off [B_*OCOFF_*HW_];
__device__ float2 g_stats[32];
// padded NHWC fp16 input / weights for conv1
__device__ __align__(128) __half g_xt[(size_t)B_*HP_*WP_*KP_];
__device__ __align__(128) __half g_wt[9*128*KP_];
// padded NHWC fp16 lr+sim (192 ch) / packed offset weights
__device__ __align__(128) __half g_ls[(size_t)B_*HP_*WP_*KO_];
__device__ __align__(128) __half g_wo[9*64*KO_];

// ---------------- ptx helpers (cp.async / ldmatrix / mma.sync) ----------------
__device__ __forceinline__ uint32_t smem_u32(const void* p) {
    uint32_t a;
    asm("{ .reg .u64 t; cvta.to.shared.u64 t, %1; cvt.u32.u64 %0, t; }" : "=r"(a) : "l"(p));
    return a;
}
__device__ __forceinline__ void cp_async16(uint32_t dst, const void* src) {
    asm volatile("cp.async.cg.shared.global [%0], [%1], 16;" :: "r"(dst), "l"(src) : "memory");
}
__device__ __forceinline__ void cpa_commit() {
    asm volatile("cp.async.commit_group;" ::: "memory");
}
template<int N> __device__ __forceinline__ void cpa_wait() {
    asm volatile("cp.async.wait_group %0;" :: "n"(N) : "memory");
}
__device__ __forceinline__ void ldm_x4(uint32_t* r, uint32_t addr) {
    asm volatile("ldmatrix.sync.aligned.m8n8.x4.shared.b16 {%0,%1,%2,%3}, [%4];"
        : "=r"(r[0]), "=r"(r[1]), "=r"(r[2]), "=r"(r[3]) : "r"(addr));
}
__device__ __forceinline__ void mma_f16(float* d, const uint32_t* a, uint32_t b0, uint32_t b1) {
    asm volatile("mma.sync.aligned.m16n8k16.row.col.f32.f16.f16.f32 "
        "{%0,%1,%2,%3}, {%4,%5,%6,%7}, {%8,%9}, {%0,%1,%2,%3};"
        : "+f"(d[0]), "+f"(d[1]), "+f"(d[2]), "+f"(d[3])
        : "r"(a[0]), "r"(a[1]), "r"(a[2]), "r"(a[3]), "r"(b0), "r"(b1));
}

// ---------------- prep: zero pad-k chunks (+inline coords), zero borders ----------------
#define PREP_T1_ (B_*HP_*WP_*8)
#define PREP_T2_ (B_*2184*120)
__global__ void prep_xt_kernel() {
    int i = blockIdx.x * 256 + threadIdx.x;
    if (i < PREP_T1_) {
        int px = i >> 3, ch = i & 7;
        char* base = (char*)g_xt + (size_t)px*(KP_*2) + 1792 + ch*16;
        uint4 v = make_uint4(0u,0u,0u,0u);
        if (ch == 0) {
            int rem = px % (HP_*WP_);
            int y = rem / WP_, x = rem - y*WP_;
            if (y >= 1 && y <= 120 && x >= 1 && x <= 360) {
                float gx = (x-1)*(2.f/(W_-1)) - 1.f;
                float gy = (y-1)*(2.f/(H_-1)) - 1.f;
                __half2 hh = __floats2half2_rn(gx, gy);
                v.x = *(uint32_t*)&hh;
            }
        }
        *(uint4*)base = v;
        return;
    }
    i -= PREP_T1_;
    if (i < PREP_T2_) {
        int ch = i % 120;
        int r = i / 120;
        int p = r % 2184;
        int b = r / 2184;
        int y, x;
        if (p < 744) { y = (p < 372) ? 0 : 121; x = p % 372; }
        else {
            int q = p - 744;
            y = 1 + q / 12;
            int m = q % 12;
            x = (m == 0) ? 0 : (360 + m);
        }
        char* base = (char*)g_xt + (((size_t)b*HP_ + y)*WP_ + x)*(KP_*2) + ch*16;
        *(uint4*)base = make_uint4(0u,0u,0u,0u);
    }
}

// ---------------- pack x (NCHW fp32 -> padded NHWC fp16) ----------------
__global__ void pack_x_kernel(const float* __restrict__ x) {
    __shared__ float t[32][33];
    int b  = blockIdx.z;
    int cg = blockIdx.y;
    int pg = blockIdx.x;
    int tx = threadIdx.x & 31, ty = threadIdx.x >> 5;
    int pix0 = pg * 32;
    const float* src = x + ((size_t)b*896 + cg*32)*HW_ + pix0;
#pragma unroll
    for (int k = 0; k < 4; k++)
        t[ty + 8*k][tx] = src[(size_t)(ty + 8*k)*HW_ + tx];
    __syncthreads();
#pragma unroll
    for (int k = 0; k < 4; k++) {
        int p = pix0 + ty + 8*k;
        int yy = p / W_, xx = p - yy*W_;
        size_t ro = (((size_t)b*HP_ + yy + 1)*WP_ + (xx + 1))*KP_ + cg*32;
        g_xt[ro + tx] = __float2half(t[tx][ty + 8*k]);
    }
}

// ---------------- pack conv1 weights (per tap, K-major, fp16) ----------------
__global__ void pack_w_kernel(const float* __restrict__ w) {
    int i = blockIdx.x * 256 + threadIdx.x;
    if (i >= 9*128*KP_) return;
    int tap = i / (128*KP_);
    int r = i - tap*(128*KP_);
    int oc = r / KP_, k = r - oc*KP_;
    float v = (k < 898) ? w[((size_t)oc*898 + k)*9 + tap] : 0.f;
    g_wt[i] = __float2half(v);
}

// ---------------- conv1: mma.sync fp16, A-reuse across kx ----------------
extern __shared__ char conv_smem[];

__global__ void __launch_bounds__(256, 2) conv1_mma_kernel(const float* __restrict__ bias) {
    const uint32_t sb = smem_u32(conv_smem);
    const int tid = threadIdx.x;
    const int b = blockIdx.z, y = blockIdx.y, x0 = blockIdx.x * 120;
    const int warp = tid >> 5, lane = tid & 31;
    const int m0 = (warp >> 1) * 32, n0 = (warp & 1) * 64;

    float acc[2][8][4];
#pragma unroll
    for (int mt = 0; mt < 2; mt++)
#pragma unroll
        for (int nt = 0; nt < 8; nt++)
#pragma unroll
            for (int e = 0; e < 4; e++) acc[mt][nt][e] = 0.f;

    const int lrow = tid >> 1, cb = (tid & 1) * 4;

    auto issueA = [&](int g, int bufi) {
        int ky = g % 3, kc = g / 3;
        const char* src0 = (const char*)(g_xt + (((size_t)b*HP_ + y + ky)*WP_ + x0)*KP_ + kc*64);
        uint32_t dstBase = sb + (uint32_t)bufi*ASZ_;
        {
            const char* s = src0 + (size_t)lrow * (KP_*2);
            uint32_t d = dstBase + (uint32_t)lrow * 128;
#pragma unroll
            for (int t = 0; t < 4; t++) {
                int c = cb + t;
                cp_async16(d + (uint32_t)((c ^ (lrow & 7)) << 4), s + c*16);
            }
        }
        if (tid < 4) {
            int r2 = 128 + (tid >> 1);
            int cb2 = (tid & 1) * 4;
            const char* s = src0 + (size_t)r2 * (KP_*2);
            uint32_t d = dstBase + (uint32_t)r2 * 128;
#pragma unroll
            for (int t = 0; t < 4; t++) {
                int c = cb2 + t;
                cp_async16(d + (uint32_t)((c ^ (r2 & 7)) << 4), s + c*16);
            }
        }
    };

    auto issueB = [&](int t) {
        int g = t / 3, s = t - g*3;
        int ky = g % 3, kc = g / 3;
        const char* src = (const char*)(g_wt + ((size_t)(ky*3 + s)*128 + lrow)*KP_ + kc*64);
        uint32_t d = sb + 2*ASZ_ + (uint32_t)(t & 1)*BSZ_ + (uint32_t)lrow * 128;
#pragma unroll
        for (int tt = 0; tt < 4; tt++) {
            int c = cb + tt;
            cp_async16(d + (uint32_t)((c ^ (lrow & 7)) << 4), src + c*16);
        }
    };

    issueA(0, 0);
    issueB(0);
    cpa_commit();

    const int gq = lane >> 3, rq = lane & 7;
    for (int t = 0; t < NSTG_; t++) {
        const int g = t / 3, s = t - g*3;
        cpa_wait<0>();
        __syncthreads();
        if (s == 0 && g + 1 < NGRP_) issueA(g + 1, (g + 1) & 1);
        if (t + 1 < NSTG_) issueB(t + 1);
        cpa_commit();

        const uint32_t As = sb + (uint32_t)(g & 1)*ASZ_;
        const uint32_t Bs = sb + 2*ASZ_ + (uint32_t)(t & 1)*BSZ_;
        const int kx = s;

#pragma unroll
        for (int kt = 0; kt < 4; kt++) {
            const int c = kt*2 + (gq >> 1);
            uint32_t a[2][4];
#pragma unroll
            for (int mt = 0; mt < 2; mt++) {
                int sr = m0 + mt*16 + ((gq & 1) << 3) + rq + kx;
                uint32_t off = (uint32_t)sr*128 + (uint32_t)((c ^ (sr & 7)) << 4);
                ldm_x4(a[mt], As + off);
            }
#pragma unroll
            for (int nt = 0; nt < 4; nt++) {
                uint32_t bq[4];
                int brow = n0 + nt*16 + ((gq & 1) << 3) + rq;
                ldm_x4(bq, Bs + (uint32_t)brow*128 + (uint32_t)((c ^ (brow & 7)) << 4));
#pragma unroll
                for (int mt = 0; mt < 2; mt++) {
                    mma_f16(acc[mt][nt*2],     a[mt], bq[0], bq[2]);
                    mma_f16(acc[mt][nt*2 + 1], a[mt], bq[1], bq[3]);
                }
            }
        }
    }

    const int qr = lane >> 2, qc = (lane & 3) * 2;
#pragma unroll
    for (int mt = 0; mt < 2; mt++) {
        int lm = m0 + mt*16 + qr;
#pragma unroll
        for (int nt = 0; nt < 8; nt++) {
            int oc = n0 + nt*8 + qc;
            float b0v = __ldg(bias + oc), b1v = __ldg(bias + oc + 1);
            float* p = g_feat + ((size_t)b*HID_ + oc)*HW_ + y*W_ + x0;
            if (lm < 120) {
                p[lm]       = fmaxf(acc[mt][nt][0] + b0v, 0.f);
                p[lm + HW_] = fmaxf(acc[mt][nt][1] + b1v, 0.f);
            }
            if (lm + 8 < 120) {
                p[lm + 8]       = fmaxf(acc[mt][nt][2] + b0v, 0.f);
                p[lm + 8 + HW_] = fmaxf(acc[mt][nt][3] + b1v, 0.f);
            }
        }
    }
}

// ---------------- mean over N ----------------
__global__ void mean_kernel(const float* __restrict__ x) {
    int i = blockIdx.x * 256 + threadIdx.x;
    if (i >= B_*C_*HW_) return;
    int b = i / (C_*HW_);
    int r = i - b*(C_*HW_);
    const float* p = x + (size_t)b*N_*C_*HW_ + r;
    float s = 0.f;
#pragma unroll
    for (int n = 0; n < N_; n++) s += p[(size_t)n*C_*HW_];
    g_mean[i] = s * (1.f/N_);
}

// ---------------- GroupNorm stats ----------------
__global__ void gn_stats_kernel() {
    __shared__ double sd[256], sd2[256];
    int bg = blockIdx.x;
    const float* p = g_mean + (size_t)bg * (8*HW_);
    double s = 0.0, ss = 0.0;
    const int n4 = (8*HW_)/4;
    for (int i = threadIdx.x; i < n4; i += 256) {
        float4 v = *(const float4*)(p + (size_t)i*4);
        s  += (double)v.x + v.y + v.z + v.w;
        ss += (double)v.x*v.x + (double)v.y*v.y + (double)v.z*v.z + (double)v.w*v.w;
    }
    sd[threadIdx.x] = s; sd2[threadIdx.x] = ss;
    __syncthreads();
    for (int o = 128; o; o >>= 1) {
        if (threadIdx.x < o) { sd[threadIdx.x] += sd[threadIdx.x+o]; sd2[threadIdx.x] += sd2[threadIdx.x+o]; }
        __syncthreads();
    }
    if (threadIdx.x == 0) {
        double n = 8.0*HW_;
        double mu = sd[0]/n;
        double var = sd2[0]/n - mu*mu;
        g_stats[bg] = make_float2((float)mu, rsqrtf((float)var + 1e-5f));
    }
}

// ---------------- GroupNorm apply + transpose + per-pixel L2 norm ----------------
// Block: 32 pixels x 128 ch for batch b. Coalesced NCHW reads, smem transpose,
// coalesced 32B NHWC fp16 writes into g_ls, per-pixel L2 norm in-block.
__global__ void __launch_bounds__(256) gn_apply_norm_kernel(
        const float* __restrict__ gamma, const float* __restrict__ beta) {
    __shared__ float s[128][33];
    const int b = blockIdx.y;
    const int pix0 = blockIdx.x * 32;
    const int tx = threadIdx.x & 31, ty = threadIdx.x >> 5;   // warp ty, lane tx
#pragma unroll
    for (int k = 0; k < 16; k++) {
        int c = ty*16 + k;
        float2 st = g_stats[b*16 + (c >> 3)];
        float m = g_mean[((size_t)(b*C_ + c))*HW_ + pix0 + tx];
        s[c][tx] = (m - st.x) * st.y * gamma[c] + beta[c];
    }
    __syncthreads();
    const int g = threadIdx.x & 7, p = threadIdx.x >> 3;   // 8 threads per pixel
    float ss = 0.f;
    __half hv[16];
#pragma unroll
    for (int j = 0; j < 16; j++) {
        float v = s[g*16 + j][p];
        ss += v*v;
        hv[j] = __float2half(v);
    }
#pragma unroll
    for (int o = 4; o; o >>= 1) ss += __shfl_xor_sync(0xffffffffu, ss, o);
    int pix = pix0 + p;
    int yy = pix / W_, xx = pix - yy*W_;
    size_t ro = (((size_t)b*HP_ + yy + 1)*WP_ + (xx + 1))*KO_ + g*16;
    *(uint4*)&g_ls[ro]     = *(uint4*)&hv[0];
    *(uint4*)&g_ls[ro + 8] = *(uint4*)&hv[8];
    if (g == 0) g_norm[b*HW_ + pix] = fmaxf(sqrtf(ss), 1e-8f);
}

// ---------------- cosine similarity (symmetric halving, fp16 operands) ----------------
__global__ void sim_kernel() {
    int wid = (blockIdx.x*256 + threadIdx.x) >> 5;
    int lane = threadIdx.x & 31;
    if (wid >= B_*HW_) return;
    int b = wid / HW_;
    int pix = wid - b*HW_;
    int y = pix / W_, xx = pix - y*W_;
    size_t crow = (((size_t)b*HP_ + y + 1)*WP_ + (xx + 1))*KO_;
    uint2 cvu = *(const uint2*)&g_ls[crow + lane*4];
    float2 c0 = __half22float2(*(__half2*)&cvu.x);
    float2 c1 = __half22float2(*(__half2*)&cvu.y);
    float inv_cn = 1.f / g_norm[wid];
    size_t po = crow + 128;
#pragma unroll
    for (int t = 0; t < 24; t++) {
        const int i = t / 7, j = t - 7*(t/7);
        int ny = y + 2*i - 6, nx = xx + 2*j - 6;
        if ((unsigned)ny < H_ && (unsigned)nx < W_) {
            int npid = b*HW_ + ny*W_ + nx;
            size_t nrow = (((size_t)b*HP_ + ny + 1)*WP_ + (nx + 1))*KO_;
            uint2 nvu = *(const uint2*)&g_ls[nrow + lane*4];
            float2 n0 = __half22float2(*(__half2*)&nvu.x);
            float2 n1 = __half22float2(*(__half2*)&nvu.y);
            float d = c0.x*n0.x + c0.y*n0.y + c1.x*n1.x + c1.y*n1.y;
#pragma unroll
            for (int o = 16; o; o >>= 1) d += __shfl_xor_sync(0xffffffffu, d, o);
            if (lane == 0) {
                float v = d * inv_cn / g_norm[npid];
                __half hvv = __float2half(v);
                g_ls[po + t] = hvv;
                g_ls[nrow + 128 + 47 - t] = hvv;
            }
        }
    }
}

// ---------------- zfill: whole g_ls buffer ----------------
__global__ void zfill_ls_kernel() {
    size_t n4 = ((size_t)B_*HP_*WP_*KO_*2) / 16;
    size_t i = (size_t)blockIdx.x * 256 + threadIdx.x;
    if (i < n4) ((uint4*)g_ls)[i] = make_uint4(0u,0u,0u,0u);
}

// ---------------- pack offset weights: [9 tap][64 oc][192 k] fp16 ----------------
__global__ void pack_wo_kernel(const float* __restrict__ w0, const float* __restrict__ w1,
                               const float* __restrict__ w2) {
    int i = blockIdx.x * 256 + threadIdx.x;
    if (i >= 9*64*KO_) return;
    int tap = i / (64*KO_);
    int r = i - tap*(64*KO_);
    int oc = r / KO_, k = r - oc*KO_;
    float v = 0.f;
    if (k < 176) {
        if (oc < 32)      v = w0[((size_t)oc*176 + k)*9 + tap];
        else if (oc < 48) v = w1[((size_t)(oc-32)*176 + k)*9 + tap];
        else if (oc < 56) v = w2[((size_t)(oc-48)*176 + k)*9 + tap];
    }
    g_wo[i] = __float2half(v);
}

// ---------------- offconv: mma.sync fp16 (K=192, N=64) ----------------
__global__ void __launch_bounds__(256, 2) offconv_mma_kernel(
        const float* __restrict__ b0a, const float* __restrict__ b1a,
        const float* __restrict__ b2a) {
    const uint32_t sb = smem_u32(conv_smem);
    const int tid = threadIdx.x;
    const int b = blockIdx.z, y = blockIdx.y, x0 = blockIdx.x * 120;
    const int warp = tid >> 5, lane = tid & 31;
    const int m0 = (warp >> 1) * 32, n0 = (warp & 1) * 32;

    float acc[2][4][4];
#pragma unroll
    for (int mt = 0; mt < 2; mt++)
#pragma unroll
        for (int nt = 0; nt < 4; nt++)
#pragma unroll
            for (int e = 0; e < 4; e++) acc[mt][nt][e] = 0.f;

    const int lrow = tid >> 1, cb = (tid & 1) * 4;

    auto issueA = [&](int g, int bufi) {
        int ky = g % 3, kc = g / 3;
        const char* src0 = (const char*)(g_ls + (((size_t)b*HP_ + y + ky)*WP_ + x0)*KO_ + kc*64);
        uint32_t dstBase = sb + (uint32_t)bufi*ASZ_;
        {
            const char* s = src0 + (size_t)lrow * (KO_*2);
            uint32_t d = dstBase + (uint32_t)lrow * 128;
#pragma unroll
            for (int t = 0; t < 4; t++) {
                int c = cb + t;
                cp_async16(d + (uint32_t)((c ^ (lrow & 7)) << 4), s + c*16);
            }
        }
        if (tid < 4) {
            int r2 = 128 + (tid >> 1);
            int cb2 = (tid & 1) * 4;
            const char* s = src0 + (size_t)r2 * (KO_*2);
            uint32_t d = dstBase + (uint32_t)r2 * 128;
#pragma unroll
            for (int t = 0; t < 4; t++) {
                int c = cb2 + t;
                cp_async16(d + (uint32_t)((c ^ (r2 & 7)) << 4), s + c*16);
            }
        }
    };

    auto issueB = [&](int t) {
        int g = t / 3, s = t - g*3;
        int ky = g % 3, kc = g / 3;
        int r = tid >> 2, cb2 = (tid & 3) * 2;
        const char* src = (const char*)(g_wo + ((size_t)(ky*3 + s)*64 + r)*KO_ + kc*64);
        uint32_t d = sb + 2*ASZ_ + (uint32_t)(t & 1)*OBSZ_ + (uint32_t)r * 128;
#pragma unroll
        for (int tt = 0; tt < 2; tt++) {
            int c = cb2 + tt;
            cp_async16(d + (uint32_t)((c ^ (r & 7)) << 4), src + c*16);
        }
    };

    issueA(0, 0);
    issueB(0);
    cpa_commit();

    const int gq = lane >> 3, rq = lane & 7;
    for (int t = 0; t < ONSTG_; t++) {
        const int g = t / 3, s = t - g*3;
        cpa_wait<0>();
        __syncthreads();
        if (s == 0 && g + 1 < 9) issueA(g + 1, (g + 1) & 1);
        if (t + 1 < ONSTG_) issueB(t + 1);
        cpa_commit();

        const uint32_t As = sb + (uint32_t)(g & 1)*ASZ_;
        const uint32_t Bs = sb + 2*ASZ_ + (uint32_t)(t & 1)*OBSZ_;
        const int kx = s;

#pragma unroll
        for (int kt = 0; kt < 4; kt++) {
            const int c = kt*2 + (gq >> 1);
            uint32_t a[2][4];
#pragma unroll
            for (int mt = 0; mt < 2; mt++) {
                int sr = m0 + mt*16 + ((gq & 1) << 3) + rq + kx;
                uint32_t off = (uint32_t)sr*128 + (uint32_t)((c ^ (sr & 7)) << 4);
                ldm_x4(a[mt], As + off);
            }
#pragma unroll
            for (int nt = 0; nt < 2; nt++) {
                uint32_t bq[4];
                int brow = n0 + nt*16 + ((gq & 1) << 3) + rq;
                ldm_x4(bq, Bs + (uint32_t)brow*128 + (uint32_t)((c ^ (brow & 7)) << 4));
#pragma unroll
                for (int mt = 0; mt < 2; mt++) {
                    mma_f16(acc[mt][nt*2],     a[mt], bq[0], bq[2]);
                    mma_f16(acc[mt][nt*2 + 1], a[mt], bq[1], bq[3]);
                }
            }
        }
    }

    const int qr = lane >> 2, qc = (lane & 3) * 2;
#pragma unroll
    for (int mt = 0; mt < 2; mt++) {
        int lm = m0 + mt*16 + qr;
#pragma unroll
        for (int nt = 0; nt < 4; nt++) {
            int oc = n0 + nt*8 + qc;
            if (oc >= OCOFF_) continue;
            float b0v = (oc   < 32) ? b0a[oc]   : (oc   < 48 ? b1a[oc-32] : b2a[oc-48]);
            float b1v = (oc+1 < 32) ? b0a[oc+1] : (oc+1 < 48 ? b1a[oc-31] : b2a[oc-47]);
            float* p = g_off + ((size_t)b*OCOFF_ + oc)*HW_ + y*W_ + x0;
            if (lm < 120) {
                p[lm]       = acc[mt][nt][0] + b0v;
                p[lm + HW_] = acc[mt][nt][1] + b1v;
            }
            if (lm + 8 < 120) {
                p[lm + 8]       = acc[mt][nt][2] + b0v;
                p[lm + 8 + HW_] = acc[mt][nt][3] + b1v;
            }
        }
    }
}

// ---------------- fused triple deformable sampling + average ----------------
__device__ __forceinline__ float bilin(const float* __restrict__ f, float ix, float iy) {
    float fx = floorf(ix), fy = floorf(iy);
    float wx = ix - fx, wy = iy - fy;
    int xl = (int)fx, yl = (int)fy;
    int x0i = min(max(xl,     0), W_-1);
    int x1i = min(max(xl + 1, 0), W_-1);
    int y0i = min(max(yl,     0), H_-1);
    int y1i = min(max(yl + 1, 0), H_-1);
    float v00 = f[y0i*W_ + x0i], v01 = f[y0i*W_ + x1i];
    float v10 = f[y1i*W_ + x0i], v11 = f[y1i*W_ + x1i];
    return (v00*(1.f-wx) + v01*wx)*(1.f-wy) + (v10*(1.f-wx) + v11*wx)*wy;
}

__global__ void sample_kernel(float* __restrict__ out) {
    int i = blockIdx.x * 256 + threadIdx.x;
    if (i >= B_*C_*HW_) return;
    int xx = i % W_;
    int y  = (i / W_) % H_;
    int c  = (i / HW_) % C_;
    int b  = i / (C_*HW_);
    const float* offp = g_off + (size_t)b*OCOFF_*HW_ + y*W_ + xx;
    float ox0 = offp[(size_t)( 0 + (c>>3))*HW_], oy0 = offp[(size_t)(16 + (c>>3))*HW_];
    float ox1 = offp[(size_t)(32 + (c>>4))*HW_], oy1 = offp[(size_t)(40 + (c>>4))*HW_];
    float ox2 = offp[(size_t)(48 + (c>>5))*HW_], oy2 = offp[(size_t)(52 + (c>>5))*HW_];
    const float* f = g_feat + (size_t)(b*HID_ + c)*HW_;
    float s = bilin(f, xx + ox0, y + oy0)
            + bilin(f, xx + ox1, y + oy1)
            + bilin(f, xx + ox2, y + oy2);
    out[i] = s * (1.f/3.f);
}

// ---------------- launch (sequential; conv1 is launch #4 for ncu) ----------------
extern "C" void kernel_launch(void* const* d_in, const int* in_sizes, int n_in,
                              void* d_out, int out_size) {
    const float* x        = (const float*)d_in[0];
    const float* conv_w   = (const float*)d_in[1];
    const float* conv_b   = (const float*)d_in[2];
    const float* gn_gamma = (const float*)d_in[3];
    const float* gn_beta  = (const float*)d_in[4];
    const float* off_w    = (const float*)d_in[5];
    const float* off_b    = (const float*)d_in[6];
    const float* off1_w   = (const float*)d_in[7];
    const float* off1_b   = (const float*)d_in[8];
    const float* off2_w   = (const float*)d_in[9];
    const float* off2_b   = (const float*)d_in[10];
    float* out = (float*)d_out;

    static bool init_done = false;
    if (!init_done) {
        cudaFuncSetAttribute(conv1_mma_kernel, cudaFuncAttributeMaxDynamicSharedMemorySize, SMEM_CONV_);
        cudaFuncSetAttribute(offconv_mma_kernel, cudaFuncAttributeMaxDynamicSharedMemorySize, SMEM_OFF_);
        init_done = true;
    }

    const int total = B_*C_*HW_;

    // conv1 path (conv1 = 4th launch for profiling)
    prep_xt_kernel<<<(PREP_T1_ + PREP_T2_ + 255)/256, 256>>>();
    pack_x_kernel<<<dim3(HW_/32, 28, B_), 256>>>(x);
    pack_w_kernel<<<(9*128*KP_ + 255)/256, 256>>>(conv_w);
    conv1_mma_kernel<<<dim3(3, 120, B_), 256, SMEM_CONV_>>>(conv_b);

    // offset path
    zfill_ls_kernel<<<(int)((((size_t)B_*HP_*WP_*KO_*2)/16 + 255)/256), 256>>>();
    pack_wo_kernel<<<(9*64*KO_ + 255)/256, 256>>>(off_w, off1_w, off2_w);
    mean_kernel<<<(total + 255)/256, 256>>>(x);
    gn_stats_kernel<<<32, 256>>>();
    gn_apply_norm_kernel<<<dim3(HW_/32, B_), 256>>>(gn_gamma, gn_beta);
    sim_kernel<<<(B_*HW_ + 7)/8, 256>>>();
    offconv_mma_kernel<<<dim3(3, 120, B_), 256, SMEM_OFF_>>>(off_b, off1_b, off2_b);
    sample_kernel<<<(total + 255)/256, 256>>>(out);
}

// round 15
// speedup vs baseline: 1.5500x; 1.5500x over previous
#include <cuda_runtime.h>
#include <cuda_bf16.h>
#include <cuda_fp16.h>
#include <cstdint>

#define B_ 2
#define N_ 7
#define C_ 128
#define H_ 120
#define W_ 360
#define HW_ (H_*W_)
#define HID_ 128
#define OCOFF_ 56

// conv1 mma geometry (single fp16 A, single fp16 B)
#define KP_ 960                    // padded K (898 -> 960, 15 chunks of 64)
#define HP_ 122
#define WP_ 372
#define ASZ_ 16640                 // A tile: 130 rows x 128B
#define BSZ_ 16384                 // B tile: 128 rows x 128B
#define NGRP_ 45                   // 15 kc x 3 ky
#define NSTG_ 135                  // 45 groups x 3 kx stages
#define SMEM_CONV_ (2*ASZ_ + 3*BSZ_)   // A x2 + B ring x3 = 82432B (occ 2)

// offconv mma geometry (K = 128 lr + 48 sim + 16 pad = 192; N = 56 -> 64)
#define KO_ 192
#define OBSZ_ 8192                 // B tile: 64 rows x 128B
#define ONSTG_ 27                  // 9 groups (3 kc x 3 ky) x 3 kx
#define SMEM_OFF_ (2*ASZ_ + 3*OBSZ_)   // 57856B

// ---------------- scratch (device globals; no runtime alloc) ----------------
__device__ float g_mean[B_*C_*HW_];
__device__ float g_norm[B_*HW_];
__device__ float g_feat[B_*HID_*HW_];
__device__ float g_off [B_*OCOFF_*HW_];
__device__ float2 g_stats[32];
// padded NHWC fp16 input / weights for conv1
__device__ __align__(128) __half g_xt[(size_t)B_*HP_*WP_*KP_];
__device__ __align__(128) __half g_wt[9*128*KP_];
// padded NHWC fp16 lr+sim (192 ch) / packed offset weights
__device__ __align__(128) __half g_ls[(size_t)B_*HP_*WP_*KO_];
__device__ __align__(128) __half g_wo[9*64*KO_];

// ---------------- ptx helpers (cp.async / ldmatrix / mma.sync) ----------------
__device__ __forceinline__ uint32_t smem_u32(const void* p) {
    uint32_t a;
    asm("{ .reg .u64 t; cvta.to.shared.u64 t, %1; cvt.u32.u64 %0, t; }" : "=r"(a) : "l"(p));
    return a;
}
__device__ __forceinline__ void cp_async16(uint32_t dst, const void* src) {
    asm volatile("cp.async.cg.shared.global [%0], [%1], 16;" :: "r"(dst), "l"(src) : "memory");
}
__device__ __forceinline__ void cpa_commit() {
    asm volatile("cp.async.commit_group;" ::: "memory");
}
template<int N> __device__ __forceinline__ void cpa_wait() {
    asm volatile("cp.async.wait_group %0;" :: "n"(N) : "memory");
}
__device__ __forceinline__ void ldm_x4(uint32_t* r, uint32_t addr) {
    asm volatile("ldmatrix.sync.aligned.m8n8.x4.shared.b16 {%0,%1,%2,%3}, [%4];"
        : "=r"(r[0]), "=r"(r[1]), "=r"(r[2]), "=r"(r[3]) : "r"(addr));
}
__device__ __forceinline__ void mma_f16(float* d, const uint32_t* a, uint32_t b0, uint32_t b1) {
    asm volatile("mma.sync.aligned.m16n8k16.row.col.f32.f16.f16.f32 "
        "{%0,%1,%2,%3}, {%4,%5,%6,%7}, {%8,%9}, {%0,%1,%2,%3};"
        : "+f"(d[0]), "+f"(d[1]), "+f"(d[2]), "+f"(d[3])
        : "r"(a[0]), "r"(a[1]), "r"(a[2]), "r"(a[3]), "r"(b0), "r"(b1));
}

// ---------------- prep: zero pad-k chunks (+inline coords), zero borders ----------------
#define PREP_T1_ (B_*HP_*WP_*8)
#define PREP_T2_ (B_*2184*120)
__global__ void prep_xt_kernel() {
    int i = blockIdx.x * 256 + threadIdx.x;
    if (i < PREP_T1_) {
        int px = i >> 3, ch = i & 7;
        char* base = (char*)g_xt + (size_t)px*(KP_*2) + 1792 + ch*16;
        uint4 v = make_uint4(0u,0u,0u,0u);
        if (ch == 0) {
            int rem = px % (HP_*WP_);
            int y = rem / WP_, x = rem - y*WP_;
            if (y >= 1 && y <= 120 && x >= 1 && x <= 360) {
                float gx = (x-1)*(2.f/(W_-1)) - 1.f;
                float gy = (y-1)*(2.f/(H_-1)) - 1.f;
                __half2 hh = __floats2half2_rn(gx, gy);
                v.x = *(uint32_t*)&hh;
            }
        }
        *(uint4*)base = v;
        return;
    }
    i -= PREP_T1_;
    if (i < PREP_T2_) {
        int ch = i % 120;
        int r = i / 120;
        int p = r % 2184;
        int b = r / 2184;
        int y, x;
        if (p < 744) { y = (p < 372) ? 0 : 121; x = p % 372; }
        else {
            int q = p - 744;
            y = 1 + q / 12;
            int m = q % 12;
            x = (m == 0) ? 0 : (360 + m);
        }
        char* base = (char*)g_xt + (((size_t)b*HP_ + y)*WP_ + x)*(KP_*2) + ch*16;
        *(uint4*)base = make_uint4(0u,0u,0u,0u);
    }
}

// ---------------- pack x (NCHW fp32 -> padded NHWC fp16) ----------------
__global__ void pack_x_kernel(const float* __restrict__ x) {
    __shared__ float t[32][33];
    int b  = blockIdx.z;
    int cg = blockIdx.y;
    int pg = blockIdx.x;
    int tx = threadIdx.x & 31, ty = threadIdx.x >> 5;
    int pix0 = pg * 32;
    const float* src = x + ((size_t)b*896 + cg*32)*HW_ + pix0;
#pragma unroll
    for (int k = 0; k < 4; k++)
        t[ty + 8*k][tx] = src[(size_t)(ty + 8*k)*HW_ + tx];
    __syncthreads();
#pragma unroll
    for (int k = 0; k < 4; k++) {
        int p = pix0 + ty + 8*k;
        int yy = p / W_, xx = p - yy*W_;
        size_t ro = (((size_t)b*HP_ + yy + 1)*WP_ + (xx + 1))*KP_ + cg*32;
        g_xt[ro + tx] = __float2half(t[tx][ty + 8*k]);
    }
}

// ---------------- pack conv1 weights (per tap, K-major, fp16) ----------------
__global__ void pack_w_kernel(const float* __restrict__ w) {
    int i = blockIdx.x * 256 + threadIdx.x;
    if (i >= 9*128*KP_) return;
    int tap = i / (128*KP_);
    int r = i - tap*(128*KP_);
    int oc = r / KP_, k = r - oc*KP_;
    float v = (k < 898) ? w[((size_t)oc*898 + k)*9 + tap] : 0.f;
    g_wt[i] = __float2half(v);
}

// ---------------- conv1: mma.sync fp16, A-reuse across kx, depth-2 pipeline ----------------
extern __shared__ char conv_smem[];

__global__ void __launch_bounds__(256, 2) conv1_mma_kernel(const float* __restrict__ bias) {
    const uint32_t sb = smem_u32(conv_smem);
    const int tid = threadIdx.x;
    const int b = blockIdx.z, y = blockIdx.y, x0 = blockIdx.x * 120;
    const int warp = tid >> 5, lane = tid & 31;
    const int m0 = (warp >> 1) * 32, n0 = (warp & 1) * 64;

    float acc[2][8][4];
#pragma unroll
    for (int mt = 0; mt < 2; mt++)
#pragma unroll
        for (int nt = 0; nt < 8; nt++)
#pragma unroll
            for (int e = 0; e < 4; e++) acc[mt][nt][e] = 0.f;

    const int lrow = tid >> 1, cb = (tid & 1) * 4;

    auto issueA = [&](int g, int bufi) {
        int ky = g % 3, kc = g / 3;
        const char* src0 = (const char*)(g_xt + (((size_t)b*HP_ + y + ky)*WP_ + x0)*KP_ + kc*64);
        uint32_t dstBase = sb + (uint32_t)bufi*ASZ_;
        {
            const char* s = src0 + (size_t)lrow * (KP_*2);
            uint32_t d = dstBase + (uint32_t)lrow * 128;
#pragma unroll
            for (int t = 0; t < 4; t++) {
                int c = cb + t;
                cp_async16(d + (uint32_t)((c ^ (lrow & 7)) << 4), s + c*16);
            }
        }
        if (tid < 4) {
            int r2 = 128 + (tid >> 1);
            int cb2 = (tid & 1) * 4;
            const char* s = src0 + (size_t)r2 * (KP_*2);
            uint32_t d = dstBase + (uint32_t)r2 * 128;
#pragma unroll
            for (int t = 0; t < 4; t++) {
                int c = cb2 + t;
                cp_async16(d + (uint32_t)((c ^ (r2 & 7)) << 4), s + c*16);
            }
        }
    };

    auto issueB = [&](int t) {
        int g = t / 3, s = t - g*3;
        int ky = g % 3, kc = g / 3;
        const char* src = (const char*)(g_wt + ((size_t)(ky*3 + s)*128 + lrow)*KP_ + kc*64);
        uint32_t d = sb + 2*ASZ_ + (uint32_t)(t % 3)*BSZ_ + (uint32_t)lrow * 128;
#pragma unroll
        for (int tt = 0; tt < 4; tt++) {
            int c = cb + tt;
            cp_async16(d + (uint32_t)((c ^ (lrow & 7)) << 4), src + c*16);
        }
    };

    // prologue: stage 0 (A g0 + B0), stage 1 (B1)
    issueA(0, 0);
    issueB(0);
    cpa_commit();
    issueB(1);
    cpa_commit();

    const int gq = lane >> 3, rq = lane & 7;
    for (int t = 0; t < NSTG_; t++) {
        const int g = t / 3, s = t - g*3;
        if (t < NSTG_ - 2) cpa_wait<1>();   // stage t guaranteed; t+1 may be in flight
        else               cpa_wait<0>();
        __syncthreads();
        const int tn = t + 2;
        if (tn < NSTG_) {
            if (tn % 3 == 0) issueA(tn / 3, (tn / 3) & 1);
            issueB(tn);
            cpa_commit();
        }

        const uint32_t As = sb + (uint32_t)(g & 1)*ASZ_;
        const uint32_t Bs = sb + 2*ASZ_ + (uint32_t)(t % 3)*BSZ_;
        const int kx = s;

#pragma unroll
        for (int kt = 0; kt < 4; kt++) {
            const int c = kt*2 + (gq >> 1);
            uint32_t a[2][4];
#pragma unroll
            for (int mt = 0; mt < 2; mt++) {
                int sr = m0 + mt*16 + ((gq & 1) << 3) + rq + kx;
                uint32_t off = (uint32_t)sr*128 + (uint32_t)((c ^ (sr & 7)) << 4);
                ldm_x4(a[mt], As + off);
            }
#pragma unroll
            for (int nt = 0; nt < 4; nt++) {
                uint32_t bq[4];
                int brow = n0 + nt*16 + ((gq & 1) << 3) + rq;
                ldm_x4(bq, Bs + (uint32_t)brow*128 + (uint32_t)((c ^ (brow & 7)) << 4));
#pragma unroll
                for (int mt = 0; mt < 2; mt++) {
                    mma_f16(acc[mt][nt*2],     a[mt], bq[0], bq[2]);
                    mma_f16(acc[mt][nt*2 + 1], a[mt], bq[1], bq[3]);
                }
            }
        }
    }

    const int qr = lane >> 2, qc = (lane & 3) * 2;
#pragma unroll
    for (int mt = 0; mt < 2; mt++) {
        int lm = m0 + mt*16 + qr;
#pragma unroll
        for (int nt = 0; nt < 8; nt++) {
            int oc = n0 + nt*8 + qc;
            float b0v = __ldg(bias + oc), b1v = __ldg(bias + oc + 1);
            float* p = g_feat + ((size_t)b*HID_ + oc)*HW_ + y*W_ + x0;
            if (lm < 120) {
                p[lm]       = fmaxf(acc[mt][nt][0] + b0v, 0.f);
                p[lm + HW_] = fmaxf(acc[mt][nt][1] + b1v, 0.f);
            }
            if (lm + 8 < 120) {
                p[lm + 8]       = fmaxf(acc[mt][nt][2] + b0v, 0.f);
                p[lm + 8 + HW_] = fmaxf(acc[mt][nt][3] + b1v, 0.f);
            }
        }
    }
}

// ---------------- mean over N ----------------
__global__ void mean_kernel(const float* __restrict__ x) {
    int i = blockIdx.x * 256 + threadIdx.x;
    if (i >= B_*C_*HW_) return;
    int b = i / (C_*HW_);
    int r = i - b*(C_*HW_);
    const float* p = x + (size_t)b*N_*C_*HW_ + r;
    float s = 0.f;
#pragma unroll
    for (int n = 0; n < N_; n++) s += p[(size_t)n*C_*HW_];
    g_mean[i] = s * (1.f/N_);
}

// ---------------- GroupNorm stats ----------------
__global__ void gn_stats_kernel() {
    __shared__ double sd[256], sd2[256];
    int bg = blockIdx.x;
    const float* p = g_mean + (size_t)bg * (8*HW_);
    double s = 0.0, ss = 0.0;
    const int n4 = (8*HW_)/4;
    for (int i = threadIdx.x; i < n4; i += 256) {
        float4 v = *(const float4*)(p + (size_t)i*4);
        s  += (double)v.x + v.y + v.z + v.w;
        ss += (double)v.x*v.x + (double)v.y*v.y + (double)v.z*v.z + (double)v.w*v.w;
    }
    sd[threadIdx.x] = s; sd2[threadIdx.x] = ss;
    __syncthreads();
    for (int o = 128; o; o >>= 1) {
        if (threadIdx.x < o) { sd[threadIdx.x] += sd[threadIdx.x+o]; sd2[threadIdx.x] += sd2[threadIdx.x+o]; }
        __syncthreads();
    }
    if (threadIdx.x == 0) {
        double n = 8.0*HW_;
        double mu = sd[0]/n;
        double var = sd2[0]/n - mu*mu;
        g_stats[bg] = make_float2((float)mu, rsqrtf((float)var + 1e-5f));
    }
}

// ---------------- GroupNorm apply + transpose + per-pixel L2 norm ----------------
__global__ void __launch_bounds__(256) gn_apply_norm_kernel(
        const float* __restrict__ gamma, const float* __restrict__ beta) {
    __shared__ float s[128][33];
    const int b = blockIdx.y;
    const int pix0 = blockIdx.x * 32;
    const int tx = threadIdx.x & 31, ty = threadIdx.x >> 5;
#pragma unroll
    for (int k = 0; k < 16; k++) {
        int c = ty*16 + k;
        float2 st = g_stats[b*16 + (c >> 3)];
        float m = g_mean[((size_t)(b*C_ + c))*HW_ + pix0 + tx];
        s[c][tx] = (m - st.x) * st.y * gamma[c] + beta[c];
    }
    __syncthreads();
    const int g = threadIdx.x & 7, p = threadIdx.x >> 3;
    float ss = 0.f;
    __half hv[16];
#pragma unroll
    for (int j = 0; j < 16; j++) {
        float v = s[g*16 + j][p];
        ss += v*v;
        hv[j] = __float2half(v);
    }
#pragma unroll
    for (int o = 4; o; o >>= 1) ss += __shfl_xor_sync(0xffffffffu, ss, o);
    int pix = pix0 + p;
    int yy = pix / W_, xx = pix - yy*W_;
    size_t ro = (((size_t)b*HP_ + yy + 1)*WP_ + (xx + 1))*KO_ + g*16;
    *(uint4*)&g_ls[ro]     = *(uint4*)&hv[0];
    *(uint4*)&g_ls[ro + 8] = *(uint4*)&hv[8];
    if (g == 0) g_norm[b*HW_ + pix] = fmaxf(sqrtf(ss), 1e-8f);
}

// ---------------- cosine similarity (symmetric halving, fp16 operands) ----------------
__global__ void sim_kernel() {
    int wid = (blockIdx.x*256 + threadIdx.x) >> 5;
    int lane = threadIdx.x & 31;
    if (wid >= B_*HW_) return;
    int b = wid / HW_;
    int pix = wid - b*HW_;
    int y = pix / W_, xx = pix - y*W_;
    size_t crow = (((size_t)b*HP_ + y + 1)*WP_ + (xx + 1))*KO_;
    uint2 cvu = *(const uint2*)&g_ls[crow + lane*4];
    float2 c0 = __half22float2(*(__half2*)&cvu.x);
    float2 c1 = __half22float2(*(__half2*)&cvu.y);
    float inv_cn = 1.f / g_norm[wid];
    size_t po = crow + 128;
#pragma unroll
    for (int t = 0; t < 24; t++) {
        const int i = t / 7, j = t - 7*(t/7);
        int ny = y + 2*i - 6, nx = xx + 2*j - 6;
        if ((unsigned)ny < H_ && (unsigned)nx < W_) {
            int npid = b*HW_ + ny*W_ + nx;
            size_t nrow = (((size_t)b*HP_ + ny + 1)*WP_ + (nx + 1))*KO_;
            uint2 nvu = *(const uint2*)&g_ls[nrow + lane*4];
            float2 n0 = __half22float2(*(__half2*)&nvu.x);
            float2 n1 = __half22float2(*(__half2*)&nvu.y);
            float d = c0.x*n0.x + c0.y*n0.y + c1.x*n1.x + c1.y*n1.y;
#pragma unroll
            for (int o = 16; o; o >>= 1) d += __shfl_xor_sync(0xffffffffu, d, o);
            if (lane == 0) {
                float v = d * inv_cn / g_norm[npid];
                __half hvv = __float2half(v);
                g_ls[po + t] = hvv;
                g_ls[nrow + 128 + 47 - t] = hvv;
            }
        }
    }
}

// ---------------- zfill: whole g_ls buffer ----------------
__global__ void zfill_ls_kernel() {
    size_t n4 = ((size_t)B_*HP_*WP_*KO_*2) / 16;
    size_t i = (size_t)blockIdx.x * 256 + threadIdx.x;
    if (i < n4) ((uint4*)g_ls)[i] = make_uint4(0u,0u,0u,0u);
}

// ---------------- pack offset weights: [9 tap][64 oc][192 k] fp16 ----------------
__global__ void pack_wo_kernel(const float* __restrict__ w0, const float* __restrict__ w1,
                               const float* __restrict__ w2) {
    int i = blockIdx.x * 256 + threadIdx.x;
    if (i >= 9*64*KO_) return;
    int tap = i / (64*KO_);
    int r = i - tap*(64*KO_);
    int oc = r / KO_, k = r - oc*KO_;
    float v = 0.f;
    if (k < 176) {
        if (oc < 32)      v = w0[((size_t)oc*176 + k)*9 + tap];
        else if (oc < 48) v = w1[((size_t)(oc-32)*176 + k)*9 + tap];
        else if (oc < 56) v = w2[((size_t)(oc-48)*176 + k)*9 + tap];
    }
    g_wo[i] = __float2half(v);
}

// ---------------- offconv: mma.sync fp16 (K=192, N=64), depth-2 pipeline ----------------
__global__ void __launch_bounds__(256, 2) offconv_mma_kernel(
        const float* __restrict__ b0a, const float* __restrict__ b1a,
        const float* __restrict__ b2a) {
    const uint32_t sb = smem_u32(conv_smem);
    const int tid = threadIdx.x;
    const int b = blockIdx.z, y = blockIdx.y, x0 = blockIdx.x * 120;
    const int warp = tid >> 5, lane = tid & 31;
    const int m0 = (warp >> 1) * 32, n0 = (warp & 1) * 32;

    float acc[2][4][4];
#pragma unroll
    for (int mt = 0; mt < 2; mt++)
#pragma unroll
        for (int nt = 0; nt < 4; nt++)
#pragma unroll
            for (int e = 0; e < 4; e++) acc[mt][nt][e] = 0.f;

    const int lrow = tid >> 1, cb = (tid & 1) * 4;

    auto issueA = [&](int g, int bufi) {
        int ky = g % 3, kc = g / 3;
        const char* src0 = (const char*)(g_ls + (((size_t)b*HP_ + y + ky)*WP_ + x0)*KO_ + kc*64);
        uint32_t dstBase = sb + (uint32_t)bufi*ASZ_;
        {
            const char* s = src0 + (size_t)lrow * (KO_*2);
            uint32_t d = dstBase + (uint32_t)lrow * 128;
#pragma unroll
            for (int t = 0; t < 4; t++) {
                int c = cb + t;
                cp_async16(d + (uint32_t)((c ^ (lrow & 7)) << 4), s + c*16);
            }
        }
        if (tid < 4) {
            int r2 = 128 + (tid >> 1);
            int cb2 = (tid & 1) * 4;
            const char* s = src0 + (size_t)r2 * (KO_*2);
            uint32_t d = dstBase + (uint32_t)r2 * 128;
#pragma unroll
            for (int t = 0; t < 4; t++) {
                int c = cb2 + t;
                cp_async16(d + (uint32_t)((c ^ (r2 & 7)) << 4), s + c*16);
            }
        }
    };

    auto issueB = [&](int t) {
        int g = t / 3, s = t - g*3;
        int ky = g % 3, kc = g / 3;
        int r = tid >> 2, cb2 = (tid & 3) * 2;
        const char* src = (const char*)(g_wo + ((size_t)(ky*3 + s)*64 + r)*KO_ + kc*64);
        uint32_t d = sb + 2*ASZ_ + (uint32_t)(t % 3)*OBSZ_ + (uint32_t)r * 128;
#pragma unroll
        for (int tt = 0; tt < 2; tt++) {
            int c = cb2 + tt;
            cp_async16(d + (uint32_t)((c ^ (r & 7)) << 4), src + c*16);
        }
    };

    issueA(0, 0);
    issueB(0);
    cpa_commit();
    issueB(1);
    cpa_commit();

    const int gq = lane >> 3, rq = lane & 7;
    for (int t = 0; t < ONSTG_; t++) {
        const int g = t / 3, s = t - g*3;
        if (t < ONSTG_ - 2) cpa_wait<1>();
        else                cpa_wait<0>();
        __syncthreads();
        const int tn = t + 2;
        if (tn < ONSTG_) {
            if (tn % 3 == 0) issueA(tn / 3, (tn / 3) & 1);
            issueB(tn);
            cpa_commit();
        }

        const uint32_t As = sb + (uint32_t)(g & 1)*ASZ_;
        const uint32_t Bs = sb + 2*ASZ_ + (uint32_t)(t % 3)*OBSZ_;
        const int kx = s;

#pragma unroll
        for (int kt = 0; kt < 4; kt++) {
            const int c = kt*2 + (gq >> 1);
            uint32_t a[2][4];
#pragma unroll
            for (int mt = 0; mt < 2; mt++) {
                int sr = m0 + mt*16 + ((gq & 1) << 3) + rq + kx;
                uint32_t off = (uint32_t)sr*128 + (uint32_t)((c ^ (sr & 7)) << 4);
                ldm_x4(a[mt], As + off);
            }
#pragma unroll
            for (int nt = 0; nt < 2; nt++) {
                uint32_t bq[4];
                int brow = n0 + nt*16 + ((gq & 1) << 3) + rq;
                ldm_x4(bq, Bs + (uint32_t)brow*128 + (uint32_t)((c ^ (brow & 7)) << 4));
#pragma unroll
                for (int mt = 0; mt < 2; mt++) {
                    mma_f16(acc[mt][nt*2],     a[mt], bq[0], bq[2]);
                    mma_f16(acc[mt][nt*2 + 1], a[mt], bq[1], bq[3]);
                }
            }
        }
    }

    const int qr = lane >> 2, qc = (lane & 3) * 2;
#pragma unroll
    for (int mt = 0; mt < 2; mt++) {
        int lm = m0 + mt*16 + qr;
#pragma unroll
        for (int nt = 0; nt < 4; nt++) {
            int oc = n0 + nt*8 + qc;
            if (oc >= OCOFF_) continue;
            float b0v = (oc   < 32) ? b0a[oc]   : (oc   < 48 ? b1a[oc-32] : b2a[oc-48]);
            float b1v = (oc+1 < 32) ? b0a[oc+1] : (oc+1 < 48 ? b1a[oc-31] : b2a[oc-47]);
            float* p = g_off + ((size_t)b*OCOFF_ + oc)*HW_ + y*W_ + x0;
            if (lm < 120) {
                p[lm]       = acc[mt][nt][0] + b0v;
                p[lm + HW_] = acc[mt][nt][1] + b1v;
            }
            if (lm + 8 < 120) {
                p[lm + 8]       = acc[mt][nt][2] + b0v;
                p[lm + 8 + HW_] = acc[mt][nt][3] + b1v;
            }
        }
    }
}

// ---------------- fused triple deformable sampling + average ----------------
__device__ __forceinline__ float bilin(const float* __restrict__ f, float ix, float iy) {
    float fx = floorf(ix), fy = floorf(iy);
    float wx = ix - fx, wy = iy - fy;
    int xl = (int)fx, yl = (int)fy;
    int x0i = min(max(xl,     0), W_-1);
    int x1i = min(max(xl + 1, 0), W_-1);
    int y0i = min(max(yl,     0), H_-1);
    int y1i = min(max(yl + 1, 0), H_-1);
    float v00 = f[y0i*W_ + x0i], v01 = f[y0i*W_ + x1i];
    float v10 = f[y1i*W_ + x0i], v11 = f[y1i*W_ + x1i];
    return (v00*(1.f-wx) + v01*wx)*(1.f-wy) + (v10*(1.f-wx) + v11*wx)*wy;
}

__global__ void sample_kernel(float* __restrict__ out) {
    int i = blockIdx.x * 256 + threadIdx.x;
    if (i >= B_*C_*HW_) return;
    int xx = i % W_;
    int y  = (i / W_) % H_;
    int c  = (i / HW_) % C_;
    int b  = i / (C_*HW_);
    const float* offp = g_off + (size_t)b*OCOFF_*HW_ + y*W_ + xx;
    float ox0 = offp[(size_t)( 0 + (c>>3))*HW_], oy0 = offp[(size_t)(16 + (c>>3))*HW_];
    float ox1 = offp[(size_t)(32 + (c>>4))*HW_], oy1 = offp[(size_t)(40 + (c>>4))*HW_];
    float ox2 = offp[(size_t)(48 + (c>>5))*HW_], oy2 = offp[(size_t)(52 + (c>>5))*HW_];
    const float* f = g_feat + (size_t)(b*HID_ + c)*HW_;
    float s = bilin(f, xx + ox0, y + oy0)
            + bilin(f, xx + ox1, y + oy1)
            + bilin(f, xx + ox2, y + oy2);
    out[i] = s * (1.f/3.f);
}

// ---------------- launch (sequential; conv1 is launch #4 for ncu) ----------------
extern "C" void kernel_launch(void* const* d_in, const int* in_sizes, int n_in,
                              void* d_out, int out_size) {
    const float* x        = (const float*)d_in[0];
    const float* conv_w   = (const float*)d_in[1];
    const float* conv_b   = (const float*)d_in[2];
    const float* gn_gamma = (const float*)d_in[3];
    const float* gn_beta  = (const float*)d_in[4];
    const float* off_w    = (const float*)d_in[5];
    const float* off_b    = (const float*)d_in[6];
    const float* off1_w   = (const float*)d_in[7];
    const float* off1_b   = (const float*)d_in[8];
    const float* off2_w   = (const float*)d_in[9];
    const float* off2_b   = (const float*)d_in[10];
    float* out = (float*)d_out;

    static bool init_done = false;
    if (!init_done) {
        cudaFuncSetAttribute(conv1_mma_kernel, cudaFuncAttributeMaxDynamicSharedMemorySize, SMEM_CONV_);
        cudaFuncSetAttribute(offconv_mma_kernel, cudaFuncAttributeMaxDynamicSharedMemorySize, SMEM_OFF_);
        init_done = true;
    }

    const int total = B_*C_*HW_;

    // conv1 path (conv1 = 4th launch for profiling)
    prep_xt_kernel<<<(PREP_T1_ + PREP_T2_ + 255)/256, 256>>>();
    pack_x_kernel<<<dim3(HW_/32, 28, B_), 256>>>(x);
    pack_w_kernel<<<(9*128*KP_ + 255)/256, 256>>>(conv_w);
    conv1_mma_kernel<<<dim3(3, 120, B_), 256, SMEM_CONV_>>>(conv_b);

    // offset path
    zfill_ls_kernel<<<(int)((((size_t)B_*HP_*WP_*KO_*2)/16 + 255)/256), 256>>>();
    pack_wo_kernel<<<(9*64*KO_ + 255)/256, 256>>>(off_w, off1_w, off2_w);
    mean_kernel<<<(total + 255)/256, 256>>>(x);
    gn_stats_kernel<<<32, 256>>>();
    gn_apply_norm_kernel<<<dim3(HW_/32, B_), 256>>>(gn_gamma, gn_beta);
    sim_kernel<<<(B_*HW_ + 7)/8, 256>>>();
    offconv_mma_kernel<<<dim3(3, 120, B_), 256, SMEM_OFF_>>>(off_b, off1_b, off2_b);
    sample_kernel<<<(total + 255)/256, 256>>>(out);
}